// round 14
// baseline (speedup 1.0000x reference)
#include <cuda_runtime.h>
#include <cuda_bf16.h>
#include <cstdint>

typedef unsigned int u32;

#define NB 4
#define CIN 256
#define CO 128
#define HIN 64
#define HH 128

// fragment-ordered weights + intermediates (device globals: allocs banned)
__device__ __align__(16) u32 g_W1H[4*64*8*32*4];   // [cls][k16][mg][lane][reg]
__device__ __align__(16) u32 g_W1L[4*64*8*32*4];
__device__ __align__(16) u32 g_W2H[9*8*8*32*4];    // [tap][k16][mg][lane][reg]
__device__ __align__(16) u32 g_W2L[9*8*8*32*4];
__device__ float g_y[(size_t)NB*CO*HH*HH];
__device__ float g_k[(size_t)NB*9*HH*HH];
__device__ __align__(16) u32 g_xph[(size_t)NB*CIN*HIN*128]; // pair-packed (x[c],x[c-1]) bf16-hi
__device__ __align__(16) u32 g_xpl[(size_t)NB*CIN*HIN*128]; // bf16-lo residual
__device__ __align__(16) u32 g_yph[(size_t)NB*64*HH*HH];    // chan-pair (y[2c2],y[2c2+1]) hi
__device__ __align__(16) u32 g_ypl[(size_t)NB*64*HH*HH];    // lo

__device__ __forceinline__ void splitpack(float v0, float v1, u32& hp, u32& lp){
    __nv_bfloat16 h0=__float2bfloat16(v0), h1=__float2bfloat16(v1);
    __nv_bfloat16 l0=__float2bfloat16(v0-__bfloat162float(h0));
    __nv_bfloat16 l1=__float2bfloat16(v1-__bfloat162float(h1));
    hp=(u32)__bfloat16_as_ushort(h0)|((u32)__bfloat16_as_ushort(h1)<<16);
    lp=(u32)__bfloat16_as_ushort(l0)|((u32)__bfloat16_as_ushort(l1)<<16);
}
__device__ __forceinline__ void mma16816(float* d, const uint4& a, u32 b0, u32 b1){
    asm volatile("mma.sync.aligned.m16n8k16.row.col.f32.bf16.bf16.f32 "
        "{%0,%1,%2,%3},{%4,%5,%6,%7},{%8,%9},{%0,%1,%2,%3};"
        : "+f"(d[0]),"+f"(d[1]),"+f"(d[2]),"+f"(d[3])
        : "r"(a.x),"r"(a.y),"r"(a.z),"r"(a.w),"r"(b0),"r"(b1));
}
__device__ __forceinline__ void mma16816_z(float* d, const uint4& a, u32 b0, u32 b1){
    asm volatile("mma.sync.aligned.m16n8k16.row.col.f32.bf16.bf16.f32 "
        "{%0,%1,%2,%3},{%4,%5,%6,%7},{%8,%9},{%10,%10,%10,%10};"
        : "=f"(d[0]),"=f"(d[1]),"=f"(d[2]),"=f"(d[3])
        : "r"(a.x),"r"(a.y),"r"(a.z),"r"(a.w),"r"(b0),"r"(b1),"f"(0.0f));
}

// ------------- preps -------------
__global__ void prep1(const float* __restrict__ w1){
    int idx = blockIdx.x*256 + threadIdx.x;
    int reg=idx&3, lane=(idx>>2)&31, mg=(idx>>7)&7, k16=(idx>>10)&63, cls=(idx>>16)&3;
    int row = mg*16 + (lane>>2) + (reg&1)*8;
    int kb  = k16*16 + (lane&3)*2 + (reg>>1)*8;
    int pp=cls>>1, qq=cls&1;
    float v[2];
#pragma unroll
    for(int kk=0;kk<2;kk++){
        int k=kb+kk, ci=k>>2, s=(k>>1)&1, t=k&1;
        int kh=(pp?0:1)+2*s, kw=(qq?0:1)+2*t;
        v[kk]=__ldg(w1 + (((size_t)ci*CO+row)*4+kh)*4+kw);
    }
    u32 hp,lp; splitpack(v[0],v[1],hp,lp);
    g_W1H[idx]=hp; g_W1L[idx]=lp;
}
__global__ void prep2(const float* __restrict__ w2){
    int idx = blockIdx.x*256 + threadIdx.x;
    int reg=idx&3, lane=(idx>>2)&31, mg=(idx>>7)&7, k16=(idx>>10)&7, ti=idx>>13;
    int row = mg*16 + (lane>>2) + (reg&1)*8;
    int cb  = k16*16 + (lane&3)*2 + (reg>>1)*8;
    float v[2];
#pragma unroll
    for(int kk=0;kk<2;kk++)
        v[kk]=__ldg(w2 + ((size_t)(cb+kk)*CO+row)*9 + 8-ti);
    u32 hp,lp; splitpack(v[0],v[1],hp,lp);
    g_W2H[idx]=hp; g_W2L[idx]=lp;
}
__global__ void xpack(const float* __restrict__ x){
    int row = blockIdx.x;              // NB*CIN*HIN
    int col = threadIdx.x;             // 0..127, valid 0..64
    if(col>64) return;
    const float* xr = x + (size_t)row*HIN;
    float v0 = (col<HIN)? __ldg(xr+col)   : 0.f;
    float v1 = (col>=1)?  __ldg(xr+col-1) : 0.f;
    u32 hp,lp; splitpack(v0,v1,hp,lp);
    g_xph[(size_t)row*128+col]=hp; g_xpl[(size_t)row*128+col]=lp;
}
__global__ void ysplit(){
    size_t i = (size_t)blockIdx.x*256 + threadIdx.x;    // NB*64*HH*HH
    int px = (int)(i & (HH*HH-1));
    int c2b = (int)(i >> 14);
    int b = c2b >> 6, c2 = c2b & 63;
    const float* yp = g_y + ((size_t)b*CO + 2*c2)*HH*HH + px;
    float v0 = yp[0], v1 = yp[(size_t)HH*HH];
    u32 hp,lp; splitpack(v0,v1,hp,lp);
    g_yph[i]=hp; g_ypl[i]=lp;
}

// ------------- PAC gaussian kernel map -------------
__global__ __launch_bounds__(256) void kmap_kernel(const float* __restrict__ guide){
    const int b=blockIdx.z, h0=blockIdx.y*16, w0=blockIdx.x*16;
    const int tx=threadIdx.x&15, ty=threadIdx.x>>4;
    __shared__ float sm[18][18];
    float acc[9];
#pragma unroll
    for(int t=0;t<9;t++) acc[t]=0.f;
    for(int c=0;c<CO;c++){
        __syncthreads();
        for(int i=threadIdx.x;i<18*18;i+=256){
            int r=i/18, col=i%18, h=h0+r-1, w=w0+col-1;
            float v=0.f;
            if((unsigned)h<HH && (unsigned)w<HH)
                v=__ldg(guide+(((size_t)b*CO+c)*HH+h)*HH+w);
            sm[r][col]=v;
        }
        __syncthreads();
        float g0=sm[ty+1][tx+1];
#pragma unroll
        for(int i3=0;i3<3;i3++)
#pragma unroll
        for(int j3=0;j3<3;j3++){
            float d=sm[ty+i3][tx+j3]-g0;
            acc[i3*3+j3]=fmaf(d,d,acc[i3*3+j3]);
        }
    }
    int h=h0+ty, w=w0+tx;
#pragma unroll
    for(int t=0;t<9;t++)
        g_k[(((size_t)b*9+t)*HH+h)*HH+w]=__expf(-0.5f*acc[t]);
}

// ------------- stage 1: pipelined implicit GEMM, M=128 N=128 K=1024 -------------
__global__ __launch_bounds__(256) void s1mma(const float* __restrict__ b1)
{
    extern __shared__ __align__(16) u32 dsm[];   // [2buf][2pln][4k16][16ng][64w] = 64KB
    const int tid=threadIdx.x, wid=tid>>5, lane=tid&31;
    const int a0=blockIdx.x*2, cls=blockIdx.y, b=blockIdx.z;
    const int pp=cls>>1, qq=cls&1;
    const int warpM=wid>>2, warpN=wid&3;
    const int bkc=wid>>1, bng0=(wid&1)*8, n8=lane>>2, q=lane&3;

    float acc[4][4][4];
#pragma unroll
    for(int i=0;i<4;i++)
#pragma unroll
    for(int j=0;j<4;j++)
#pragma unroll
    for(int r=0;r<4;r++) acc[i][j][r]=0.f;

    u32 ph[16], pl[16];
    auto pre=[&](int cc){
#pragma unroll
        for(int gi=0;gi<8;gi++){
            int n=(bng0+gi)*8+n8, ai=n>>6, bb=n&63;
#pragma unroll
            for(int j=0;j<2;j++){
                int kg=cc*64+bkc*16+q*2+j*8;
                int ci=kg>>2, s=(kg>>1)&1;
                int rowx=a0+ai+pp-s;
                bool rv=(unsigned)rowx<HIN;
                size_t off=(((size_t)b*CIN+ci)*HIN+(rv?rowx:0))*128 + bb+qq;
                ph[gi*2+j]=rv?__ldg(g_xph+off):0u;
                pl[gi*2+j]=rv?__ldg(g_xpl+off):0u;
            }
        }
    };
    pre(0);
    for(int cc=0;cc<16;cc++){
        int buf=cc&1;
        u32 wb = buf*8192 + bkc*1024;
#pragma unroll
        for(int gi=0;gi<8;gi++){
            int ng=bng0+gi;
            *(uint2*)&dsm[wb + ng*64 + lane*2]        = make_uint2(ph[gi*2],ph[gi*2+1]);
            *(uint2*)&dsm[wb + 4096 + ng*64 + lane*2] = make_uint2(pl[gi*2],pl[gi*2+1]);
        }
        __syncthreads();
        if(cc<15) pre(cc+1);
#pragma unroll
        for(int ks=0;ks<4;ks++){
            u32 abase=((((u32)cls*64 + cc*4+ks)*8 + warpM*4)*32 + lane)*4;
            uint4 ah[4], al[4];
#pragma unroll
            for(int mi=0;mi<4;mi++){
                ah[mi]=*(const uint4*)&g_W1H[abase+mi*128];
                al[mi]=*(const uint4*)&g_W1L[abase+mi*128];
            }
#pragma unroll
            for(int nj=0;nj<4;nj++){
                int ng=warpN*4+nj;
                uint2 bh=*(const uint2*)&dsm[buf*8192 + ks*1024 + ng*64 + lane*2];
                uint2 bl=*(const uint2*)&dsm[buf*8192 + 4096 + ks*1024 + ng*64 + lane*2];
#pragma unroll
                for(int mi=0;mi<4;mi++){
                    mma16816(acc[mi][nj], ah[mi], bh.x, bh.y);
                    mma16816(acc[mi][nj], ah[mi], bl.x, bl.y);
                    mma16816(acc[mi][nj], al[mi], bh.x, bh.y);
                }
            }
        }
    }
    // epilogue: bias + scatter to NCHW y
#pragma unroll
    for(int mi=0;mi<4;mi++){
        int cob = warpM*64+mi*16+(lane>>2);
        float bias0=__ldg(b1+cob), bias1=__ldg(b1+cob+8);
#pragma unroll
        for(int nj=0;nj<4;nj++)
#pragma unroll
        for(int r=0;r<4;r++){
            int co = cob + (r>>1)*8;
            int n  = warpN*32+nj*8+(lane&3)*2+(r&1);
            int ai=n>>6, bb=n&63;
            int oh=2*(a0+ai)+pp, ow=2*bb+qq;
            g_y[(((size_t)b*CO+co)*HH+oh)*HH+ow] = acc[mi][nj][r] + ((r>>1)?bias1:bias0);
        }
    }
}

// ------------- stage 2: pipelined, per-tap GEMM + register k-fold -------------
__global__ __launch_bounds__(256) void s2mma(
    const float* __restrict__ b2, float* __restrict__ out)
{
    extern __shared__ __align__(16) u32 dsm[];   // 64KB B bufs + 4.5KB ksm
    float* ksm = (float*)(dsm + 16384);
    const int tid=threadIdx.x, wid=tid>>5, lane=tid&31;
    const int h=blockIdx.x, b=blockIdx.y;
    const int warpM=wid>>2, warpN=wid&3;
    const int bkc=wid>>1, bng0=(wid&1)*8, n8=lane>>2, q=lane&3;

    for(int i=tid;i<9*128;i+=256){
        int ti=i>>7, n=i&127;
        ksm[i]=__ldg(&g_k[(((size_t)b*9+ti)*HH+h)*HH+n]);
    }
    __syncthreads();

    float acc[4][4][4], acct[4][4][4];
#pragma unroll
    for(int i=0;i<4;i++)
#pragma unroll
    for(int j=0;j<4;j++)
#pragma unroll
    for(int r=0;r<4;r++) acc[i][j][r]=0.f;

    u32 ph[16], pl[16];
    auto pre=[&](int cc){
        int ti=cc>>1, chalf=(cc&1)*64;
        int dh=ti/3-1, dw=ti-(ti/3)*3-1;
        int hh=h+dh; bool hv=(unsigned)hh<HH;
#pragma unroll
        for(int gi=0;gi<8;gi++){
            int n=(bng0+gi)*8+n8, col=n+dw;
            bool cv=hv && (unsigned)col<HH;
#pragma unroll
            for(int j=0;j<2;j++){
                int c2=(chalf>>1)+bkc*8+q+j*4;
                size_t off=(((size_t)b*64+c2)*HH+(hv?hh:0))*HH+(cv?col:0);
                ph[gi*2+j]=cv?__ldg(g_yph+off):0u;
                pl[gi*2+j]=cv?__ldg(g_ypl+off):0u;
            }
        }
    };
    pre(0);
    for(int t=0;t<9;t++){
#pragma unroll
        for(int half=0;half<2;half++){
            int cc=t*2+half, buf=cc&1;
            u32 wb = buf*8192 + bkc*1024;
#pragma unroll
            for(int gi=0;gi<8;gi++){
                int ng=bng0+gi;
                *(uint2*)&dsm[wb + ng*64 + lane*2]        = make_uint2(ph[gi*2],ph[gi*2+1]);
                *(uint2*)&dsm[wb + 4096 + ng*64 + lane*2] = make_uint2(pl[gi*2],pl[gi*2+1]);
            }
            __syncthreads();
            if(cc<17) pre(cc+1);
#pragma unroll
            for(int ks=0;ks<4;ks++){
                u32 abase=((((u32)t*8 + half*4 + ks)*8 + warpM*4)*32 + lane)*4;
                uint4 ah[4], al[4];
#pragma unroll
                for(int mi=0;mi<4;mi++){
                    ah[mi]=*(const uint4*)&g_W2H[abase+mi*128];
                    al[mi]=*(const uint4*)&g_W2L[abase+mi*128];
                }
#pragma unroll
                for(int nj=0;nj<4;nj++){
                    int ng=warpN*4+nj;
                    uint2 bh=*(const uint2*)&dsm[buf*8192 + ks*1024 + ng*64 + lane*2];
                    uint2 bl=*(const uint2*)&dsm[buf*8192 + 4096 + ks*1024 + ng*64 + lane*2];
#pragma unroll
                    for(int mi=0;mi<4;mi++){
                        if(half==0 && ks==0) mma16816_z(acct[mi][nj], ah[mi], bh.x, bh.y);
                        else                 mma16816(acct[mi][nj], ah[mi], bh.x, bh.y);
                        mma16816(acct[mi][nj], ah[mi], bl.x, bl.y);
                        mma16816(acct[mi][nj], al[mi], bh.x, bh.y);
                    }
                }
            }
        }
        // register k-fold: acc += k[t,n] * acct
#pragma unroll
        for(int nj=0;nj<4;nj++){
            float2 kv=*(const float2*)&ksm[t*128 + warpN*32+nj*8+(lane&3)*2];
#pragma unroll
            for(int mi=0;mi<4;mi++){
                acc[mi][nj][0]=fmaf(kv.x,acct[mi][nj][0],acc[mi][nj][0]);
                acc[mi][nj][1]=fmaf(kv.y,acct[mi][nj][1],acc[mi][nj][1]);
                acc[mi][nj][2]=fmaf(kv.x,acct[mi][nj][2],acc[mi][nj][2]);
                acc[mi][nj][3]=fmaf(kv.y,acct[mi][nj][3],acc[mi][nj][3]);
            }
        }
    }
    // epilogue
#pragma unroll
    for(int mi=0;mi<4;mi++){
        int ob = warpM*64+mi*16+(lane>>2);
        float bias0=__ldg(b2+ob), bias1=__ldg(b2+ob+8);
#pragma unroll
        for(int nj=0;nj<4;nj++)
#pragma unroll
        for(int r=0;r<4;r++){
            int o = ob + (r>>1)*8;
            int n = warpN*32+nj*8+(lane&3)*2+(r&1);
            out[(((size_t)b*CO+o)*HH+h)*HH+n] = acc[mi][nj][r] + ((r>>1)?bias1:bias0);
        }
    }
}

// ---------------------------------------------------------------------------
extern "C" void kernel_launch(void* const* d_in, const int* in_sizes, int n_in,
                              void* d_out, int out_size)
{
    (void)in_sizes;(void)n_in;(void)out_size;
    const float* x     =(const float*)d_in[0];
    const float* guide =(const float*)d_in[1];
    const float* w1    =(const float*)d_in[2];
    const float* b1    =(const float*)d_in[3];
    const float* w2    =(const float*)d_in[4];
    const float* b2    =(const float*)d_in[5];
    float* out=(float*)d_out;

    static bool attr_done=false;
    if(!attr_done){
        cudaFuncSetAttribute(s1mma, cudaFuncAttributeMaxDynamicSharedMemorySize, 65536);
        cudaFuncSetAttribute(s2mma, cudaFuncAttributeMaxDynamicSharedMemorySize, 70144);
        attr_done=true;
    }

    xpack<<<NB*CIN*HIN,128>>>(x);
    prep1<<<1024,256>>>(w1);
    prep2<<<288,256>>>(w2);
    kmap_kernel<<<dim3(8,8,NB),256>>>(guide);
    s1mma<<<dim3(32,4,NB),256,65536>>>(b1);
    ysplit<<<16384,256>>>();
    s2mma<<<dim3(HH,NB),256,70144>>>(b2,out);
}

// round 15
// speedup vs baseline: 1.1399x; 1.1399x over previous
#include <cuda_runtime.h>
#include <cuda_bf16.h>
#include <cstdint>

typedef unsigned int u32;

#define NB 4
#define CIN 256
#define CO 128
#define HIN 64
#define HH 128

// fragment-ordered weights + intermediates (device globals: allocs banned)
__device__ __align__(16) u32 g_W1H[4*64*8*32*4];   // [cls][k16][mg][lane][reg]
__device__ __align__(16) u32 g_W1L[4*64*8*32*4];
__device__ __align__(16) u32 g_W2H[9*8*8*32*4];    // [tap][k16][mg][lane][reg]
__device__ __align__(16) u32 g_W2L[9*8*8*32*4];
__device__ float g_y[(size_t)NB*CO*HH*HH];
__device__ float g_k[(size_t)NB*9*HH*HH];
__device__ __align__(16) u32 g_xph[(size_t)NB*CIN*HIN*128]; // pair-packed (x[c],x[c-1]) bf16-hi
__device__ __align__(16) u32 g_xpl[(size_t)NB*CIN*HIN*128]; // bf16-lo residual
__device__ __align__(16) u32 g_yph[(size_t)NB*64*HH*HH];    // chan-pair (y[2c2],y[2c2+1]) hi
__device__ __align__(16) u32 g_ypl[(size_t)NB*64*HH*HH];    // lo

__device__ __forceinline__ void splitpack(float v0, float v1, u32& hp, u32& lp){
    __nv_bfloat16 h0=__float2bfloat16(v0), h1=__float2bfloat16(v1);
    __nv_bfloat16 l0=__float2bfloat16(v0-__bfloat162float(h0));
    __nv_bfloat16 l1=__float2bfloat16(v1-__bfloat162float(h1));
    hp=(u32)__bfloat16_as_ushort(h0)|((u32)__bfloat16_as_ushort(h1)<<16);
    lp=(u32)__bfloat16_as_ushort(l0)|((u32)__bfloat16_as_ushort(l1)<<16);
}
__device__ __forceinline__ void mma16816(float* d, const uint4& a, u32 b0, u32 b1){
    asm volatile("mma.sync.aligned.m16n8k16.row.col.f32.bf16.bf16.f32 "
        "{%0,%1,%2,%3},{%4,%5,%6,%7},{%8,%9},{%0,%1,%2,%3};"
        : "+f"(d[0]),"+f"(d[1]),"+f"(d[2]),"+f"(d[3])
        : "r"(a.x),"r"(a.y),"r"(a.z),"r"(a.w),"r"(b0),"r"(b1));
}
__device__ __forceinline__ void mma16816_z(float* d, const uint4& a, u32 b0, u32 b1){
    asm volatile("mma.sync.aligned.m16n8k16.row.col.f32.bf16.bf16.f32 "
        "{%0,%1,%2,%3},{%4,%5,%6,%7},{%8,%9},{%10,%10,%10,%10};"
        : "=f"(d[0]),"=f"(d[1]),"=f"(d[2]),"=f"(d[3])
        : "r"(a.x),"r"(a.y),"r"(a.z),"r"(a.w),"r"(b0),"r"(b1),"f"(0.0f));
}

// ------------- preps -------------
__global__ void prep1(const float* __restrict__ w1){
    int idx = blockIdx.x*256 + threadIdx.x;
    int reg=idx&3, lane=(idx>>2)&31, mg=(idx>>7)&7, k16=(idx>>10)&63, cls=(idx>>16)&3;
    int row = mg*16 + (lane>>2) + (reg&1)*8;
    int kb  = k16*16 + (lane&3)*2 + (reg>>1)*8;
    int pp=cls>>1, qq=cls&1;
    float v[2];
#pragma unroll
    for(int kk=0;kk<2;kk++){
        int k=kb+kk, ci=k>>2, s=(k>>1)&1, t=k&1;
        int kh=(pp?0:1)+2*s, kw=(qq?0:1)+2*t;
        v[kk]=__ldg(w1 + (((size_t)ci*CO+row)*4+kh)*4+kw);
    }
    u32 hp,lp; splitpack(v[0],v[1],hp,lp);
    g_W1H[idx]=hp; g_W1L[idx]=lp;
}
__global__ void prep2(const float* __restrict__ w2){
    int idx = blockIdx.x*256 + threadIdx.x;
    int reg=idx&3, lane=(idx>>2)&31, mg=(idx>>7)&7, k16=(idx>>10)&7, ti=idx>>13;
    int row = mg*16 + (lane>>2) + (reg&1)*8;
    int cb  = k16*16 + (lane&3)*2 + (reg>>1)*8;
    float v[2];
#pragma unroll
    for(int kk=0;kk<2;kk++)
        v[kk]=__ldg(w2 + ((size_t)(cb+kk)*CO+row)*9 + 8-ti);
    u32 hp,lp; splitpack(v[0],v[1],hp,lp);
    g_W2H[idx]=hp; g_W2L[idx]=lp;
}
__global__ void xpack(const float* __restrict__ x){
    int row = blockIdx.x;              // NB*CIN*HIN
    int col = threadIdx.x;             // 0..127, valid 0..64
    if(col>64) return;
    const float* xr = x + (size_t)row*HIN;
    float v0 = (col<HIN)? __ldg(xr+col)   : 0.f;
    float v1 = (col>=1)?  __ldg(xr+col-1) : 0.f;
    u32 hp,lp; splitpack(v0,v1,hp,lp);
    g_xph[(size_t)row*128+col]=hp; g_xpl[(size_t)row*128+col]=lp;
}
__global__ void ysplit(){
    size_t i = (size_t)blockIdx.x*256 + threadIdx.x;    // NB*64*HH*HH
    int px = (int)(i & (HH*HH-1));
    int c2b = (int)(i >> 14);
    int b = c2b >> 6, c2 = c2b & 63;
    const float* yp = g_y + ((size_t)b*CO + 2*c2)*HH*HH + px;
    float v0 = yp[0], v1 = yp[(size_t)HH*HH];
    u32 hp,lp; splitpack(v0,v1,hp,lp);
    g_yph[i]=hp; g_ypl[i]=lp;
}

// ------------- PAC gaussian kernel map: no smem, no syncs, MLP-rich -------------
__global__ __launch_bounds__(128) void kmap_kernel(const float* __restrict__ guide){
    const int b = blockIdx.y;
    const int h = blockIdx.x;           // 0..127
    const int w = threadIdx.x;          // 0..127
    const bool up=h>0, dn=h<HH-1, lf=w>0, rt=w<HH-1;

    float acc[9];
#pragma unroll
    for(int t=0;t<9;t++) acc[t]=0.f;

    const float* gb = guide + ((size_t)b*CO)*HH*HH + (size_t)h*HH + w;
#pragma unroll 2
    for(int c=0;c<CO;c++){
        const float* p = gb + (size_t)c*HH*HH;
        float g0 = __ldg(p);
        float v0 = (up&&lf)? __ldg(p-HH-1):0.f;
        float v1 =  up     ? __ldg(p-HH)  :0.f;
        float v2 = (up&&rt)? __ldg(p-HH+1):0.f;
        float v3 =  lf     ? __ldg(p-1)   :0.f;
        float v5 =  rt     ? __ldg(p+1)   :0.f;
        float v6 = (dn&&lf)? __ldg(p+HH-1):0.f;
        float v7 =  dn     ? __ldg(p+HH)  :0.f;
        float v8 = (dn&&rt)? __ldg(p+HH+1):0.f;
        float d;
        d=v0-g0; acc[0]=fmaf(d,d,acc[0]);
        d=v1-g0; acc[1]=fmaf(d,d,acc[1]);
        d=v2-g0; acc[2]=fmaf(d,d,acc[2]);
        d=v3-g0; acc[3]=fmaf(d,d,acc[3]);
        d=v5-g0; acc[5]=fmaf(d,d,acc[5]);
        d=v6-g0; acc[6]=fmaf(d,d,acc[6]);
        d=v7-g0; acc[7]=fmaf(d,d,acc[7]);
        d=v8-g0; acc[8]=fmaf(d,d,acc[8]);
    }
#pragma unroll
    for(int t=0;t<9;t++)
        g_k[((size_t)b*9+t)*HH*HH + (size_t)h*HH + w] = __expf(-0.5f*acc[t]);
}

// ------------- stage 1: pipelined implicit GEMM, M=128 N=128 K=1024 -------------
__global__ __launch_bounds__(256) void s1mma(const float* __restrict__ b1)
{
    extern __shared__ __align__(16) u32 dsm[];   // [2buf][2pln][4k16][16ng][64w] = 64KB
    const int tid=threadIdx.x, wid=tid>>5, lane=tid&31;
    const int a0=blockIdx.x*2, cls=blockIdx.y, b=blockIdx.z;
    const int pp=cls>>1, qq=cls&1;
    const int warpM=wid>>2, warpN=wid&3;
    const int bkc=wid>>1, bng0=(wid&1)*8, n8=lane>>2, q=lane&3;

    float acc[4][4][4];
#pragma unroll
    for(int i=0;i<4;i++)
#pragma unroll
    for(int j=0;j<4;j++)
#pragma unroll
    for(int r=0;r<4;r++) acc[i][j][r]=0.f;

    u32 ph[16], pl[16];
    auto pre=[&](int cc){
#pragma unroll
        for(int gi=0;gi<8;gi++){
            int n=(bng0+gi)*8+n8, ai=n>>6, bb=n&63;
#pragma unroll
            for(int j=0;j<2;j++){
                int kg=cc*64+bkc*16+q*2+j*8;
                int ci=kg>>2, s=(kg>>1)&1;
                int rowx=a0+ai+pp-s;
                bool rv=(unsigned)rowx<HIN;
                size_t off=(((size_t)b*CIN+ci)*HIN+(rv?rowx:0))*128 + bb+qq;
                ph[gi*2+j]=rv?__ldg(g_xph+off):0u;
                pl[gi*2+j]=rv?__ldg(g_xpl+off):0u;
            }
        }
    };
    pre(0);
    for(int cc=0;cc<16;cc++){
        int buf=cc&1;
        u32 wb = buf*8192 + bkc*1024;
#pragma unroll
        for(int gi=0;gi<8;gi++){
            int ng=bng0+gi;
            *(uint2*)&dsm[wb + ng*64 + lane*2]        = make_uint2(ph[gi*2],ph[gi*2+1]);
            *(uint2*)&dsm[wb + 4096 + ng*64 + lane*2] = make_uint2(pl[gi*2],pl[gi*2+1]);
        }
        __syncthreads();
        if(cc<15) pre(cc+1);
#pragma unroll
        for(int ks=0;ks<4;ks++){
            u32 abase=((((u32)cls*64 + cc*4+ks)*8 + warpM*4)*32 + lane)*4;
            uint4 ah[4], al[4];
#pragma unroll
            for(int mi=0;mi<4;mi++){
                ah[mi]=*(const uint4*)&g_W1H[abase+mi*128];
                al[mi]=*(const uint4*)&g_W1L[abase+mi*128];
            }
#pragma unroll
            for(int nj=0;nj<4;nj++){
                int ng=warpN*4+nj;
                uint2 bh=*(const uint2*)&dsm[buf*8192 + ks*1024 + ng*64 + lane*2];
                uint2 bl=*(const uint2*)&dsm[buf*8192 + 4096 + ks*1024 + ng*64 + lane*2];
#pragma unroll
                for(int mi=0;mi<4;mi++){
                    mma16816(acc[mi][nj], ah[mi], bh.x, bh.y);
                    mma16816(acc[mi][nj], ah[mi], bl.x, bl.y);
                    mma16816(acc[mi][nj], al[mi], bh.x, bh.y);
                }
            }
        }
    }
    // epilogue: bias + scatter to NCHW y
#pragma unroll
    for(int mi=0;mi<4;mi++){
        int cob = warpM*64+mi*16+(lane>>2);
        float bias0=__ldg(b1+cob), bias1=__ldg(b1+cob+8);
#pragma unroll
        for(int nj=0;nj<4;nj++)
#pragma unroll
        for(int r=0;r<4;r++){
            int co = cob + (r>>1)*8;
            int n  = warpN*32+nj*8+(lane&3)*2+(r&1);
            int ai=n>>6, bb=n&63;
            int oh=2*(a0+ai)+pp, ow=2*bb+qq;
            g_y[(((size_t)b*CO+co)*HH+oh)*HH+ow] = acc[mi][nj][r] + ((r>>1)?bias1:bias0);
        }
    }
}

// ------------- stage 2: pipelined, per-tap GEMM + register k-fold -------------
__global__ __launch_bounds__(256) void s2mma(
    const float* __restrict__ b2, float* __restrict__ out)
{
    extern __shared__ __align__(16) u32 dsm[];   // 64KB B bufs + 4.5KB ksm
    float* ksm = (float*)(dsm + 16384);
    const int tid=threadIdx.x, wid=tid>>5, lane=tid&31;
    const int h=blockIdx.x, b=blockIdx.y;
    const int warpM=wid>>2, warpN=wid&3;
    const int bkc=wid>>1, bng0=(wid&1)*8, n8=lane>>2, q=lane&3;

    for(int i=tid;i<9*128;i+=256){
        int ti=i>>7, n=i&127;
        ksm[i]=__ldg(&g_k[(((size_t)b*9+ti)*HH+h)*HH+n]);
    }
    __syncthreads();

    float acc[4][4][4], acct[4][4][4];
#pragma unroll
    for(int i=0;i<4;i++)
#pragma unroll
    for(int j=0;j<4;j++)
#pragma unroll
    for(int r=0;r<4;r++) acc[i][j][r]=0.f;

    u32 ph[16], pl[16];
    auto pre=[&](int cc){
        int ti=cc>>1, chalf=(cc&1)*64;
        int dh=ti/3-1, dw=ti-(ti/3)*3-1;
        int hh=h+dh; bool hv=(unsigned)hh<HH;
#pragma unroll
        for(int gi=0;gi<8;gi++){
            int n=(bng0+gi)*8+n8, col=n+dw;
            bool cv=hv && (unsigned)col<HH;
#pragma unroll
            for(int j=0;j<2;j++){
                int c2=(chalf>>1)+bkc*8+q+j*4;
                size_t off=(((size_t)b*64+c2)*HH+(hv?hh:0))*HH+(cv?col:0);
                ph[gi*2+j]=cv?__ldg(g_yph+off):0u;
                pl[gi*2+j]=cv?__ldg(g_ypl+off):0u;
            }
        }
    };
    pre(0);
    for(int t=0;t<9;t++){
#pragma unroll
        for(int half=0;half<2;half++){
            int cc=t*2+half, buf=cc&1;
            u32 wb = buf*8192 + bkc*1024;
#pragma unroll
            for(int gi=0;gi<8;gi++){
                int ng=bng0+gi;
                *(uint2*)&dsm[wb + ng*64 + lane*2]        = make_uint2(ph[gi*2],ph[gi*2+1]);
                *(uint2*)&dsm[wb + 4096 + ng*64 + lane*2] = make_uint2(pl[gi*2],pl[gi*2+1]);
            }
            __syncthreads();
            if(cc<17) pre(cc+1);
#pragma unroll
            for(int ks=0;ks<4;ks++){
                u32 abase=((((u32)t*8 + half*4 + ks)*8 + warpM*4)*32 + lane)*4;
                uint4 ah[4], al[4];
#pragma unroll
                for(int mi=0;mi<4;mi++){
                    ah[mi]=*(const uint4*)&g_W2H[abase+mi*128];
                    al[mi]=*(const uint4*)&g_W2L[abase+mi*128];
                }
#pragma unroll
                for(int nj=0;nj<4;nj++){
                    int ng=warpN*4+nj;
                    uint2 bh=*(const uint2*)&dsm[buf*8192 + ks*1024 + ng*64 + lane*2];
                    uint2 bl=*(const uint2*)&dsm[buf*8192 + 4096 + ks*1024 + ng*64 + lane*2];
#pragma unroll
                    for(int mi=0;mi<4;mi++){
                        if(half==0 && ks==0) mma16816_z(acct[mi][nj], ah[mi], bh.x, bh.y);
                        else                 mma16816(acct[mi][nj], ah[mi], bh.x, bh.y);
                        mma16816(acct[mi][nj], ah[mi], bl.x, bl.y);
                        mma16816(acct[mi][nj], al[mi], bh.x, bh.y);
                    }
                }
            }
        }
        // register k-fold: acc += k[t,n] * acct
#pragma unroll
        for(int nj=0;nj<4;nj++){
            float2 kv=*(const float2*)&ksm[t*128 + warpN*32+nj*8+(lane&3)*2];
#pragma unroll
            for(int mi=0;mi<4;mi++){
                acc[mi][nj][0]=fmaf(kv.x,acct[mi][nj][0],acc[mi][nj][0]);
                acc[mi][nj][1]=fmaf(kv.y,acct[mi][nj][1],acc[mi][nj][1]);
                acc[mi][nj][2]=fmaf(kv.x,acct[mi][nj][2],acc[mi][nj][2]);
                acc[mi][nj][3]=fmaf(kv.y,acct[mi][nj][3],acc[mi][nj][3]);
            }
        }
    }
    // epilogue
#pragma unroll
    for(int mi=0;mi<4;mi++){
        int ob = warpM*64+mi*16+(lane>>2);
        float bias0=__ldg(b2+ob), bias1=__ldg(b2+ob+8);
#pragma unroll
        for(int nj=0;nj<4;nj++)
#pragma unroll
        for(int r=0;r<4;r++){
            int o = ob + (r>>1)*8;
            int n = warpN*32+nj*8+(lane&3)*2+(r&1);
            out[(((size_t)b*CO+o)*HH+h)*HH+n] = acc[mi][nj][r] + ((r>>1)?bias1:bias0);
        }
    }
}

// ---------------------------------------------------------------------------
extern "C" void kernel_launch(void* const* d_in, const int* in_sizes, int n_in,
                              void* d_out, int out_size)
{
    (void)in_sizes;(void)n_in;(void)out_size;
    const float* x     =(const float*)d_in[0];
    const float* guide =(const float*)d_in[1];
    const float* w1    =(const float*)d_in[2];
    const float* b1    =(const float*)d_in[3];
    const float* w2    =(const float*)d_in[4];
    const float* b2    =(const float*)d_in[5];
    float* out=(float*)d_out;

    static bool attr_done=false;
    if(!attr_done){
        cudaFuncSetAttribute(s1mma, cudaFuncAttributeMaxDynamicSharedMemorySize, 65536);
        cudaFuncSetAttribute(s2mma, cudaFuncAttributeMaxDynamicSharedMemorySize, 70144);
        attr_done=true;
    }

    xpack<<<NB*CIN*HIN,128>>>(x);
    prep1<<<1024,256>>>(w1);
    prep2<<<288,256>>>(w2);
    kmap_kernel<<<dim3(HH,NB),128>>>(guide);
    s1mma<<<dim3(32,4,NB),256,65536>>>(b1);
    ysplit<<<16384,256>>>();
    s2mma<<<dim3(HH,NB),256,70144>>>(b2,out);
}